// round 11
// baseline (speedup 1.0000x reference)
#include <cuda_runtime.h>
#include <math.h>

// B=128, L=8192, NF=16, D=256, NC=4; bins k={23,68,137,273}
//   d_in[0] input_sequence (B,L,NF) f32  -- only channel 0 used
//   d_in[1] hidden_states UNUSED; d_in[2] cycle_weights; d_in[3] proj_w (D,8); d_in[4] proj_b
// Output: (B,D) f32
//
// Key insight: whole tensor = 67MB = exactly the mandatory DRAM traffic of
// the stride-64B channel-0 gather (64B DRAM atom/element). So read the WHOLE
// tensor fully coalesced (LDG.128 dense stream): same DRAM bytes, but 4
// wavefronts/512B instead of 16 wavefronts/128B-useful -> higher achieved BW.
// Lanes whose float4 starts at a 64B boundary (gid%4==0) hold channel 0 in
// .x and accumulate; other lanes only feed the coalesced stream.

#define BB   128
#define LL   8192
#define NFF  16
#define DD   256
#define NCC  4
#define TPB  1024
#define NF4  (LL * NFF / 4)       // float4s per batch = 32768
#define OUTER 8
#define INNER 4                    // OUTER*INNER*TPB = 32768

__global__ __launch_bounds__(TPB)
void cycle_detector_kernel(const float* __restrict__ seq,
                           const float* __restrict__ cw,
                           const float* __restrict__ pw,   // (D, 8) row-major
                           const float* __restrict__ pb,
                           float* __restrict__ out)
{
    const int b   = blockIdx.x;
    const int tid = threadIdx.x;

    const int KIDX[NCC] = {23, 68, 137, 273};
    const float TWO_PI = 6.28318530717958647692f;

    const float4* base4 = (const float4*)(seq + (size_t)b * (size_t)(LL * NFF));

    // Active lanes: gid % 4 == 0  <=>  tid % 4 == 0 (stride 1024 is mult of 4).
    const bool active = ((tid & 3) == 0);
    // Active thread handles elements t = tid/4 + n*256, n = 0..31.
    const int t0 = tid >> 2;

    float re[NCC], im[NCC];
    float cr[NCC], ci[NCC];
    float dr[NCC], di[NCC];
#pragma unroll
    for (int j = 0; j < NCC; j++) {
        re[j] = 0.0f; im[j] = 0.0f;
        int m0 = (KIDX[j] * t0) & (LL - 1);
        float th0 = -TWO_PI * (float)m0 * (1.0f / (float)LL);
        sincosf(th0, &ci[j], &cr[j]);
        int md = (KIDX[j] * 256) & (LL - 1);   // t advances by 256 per float4-iter
        float thd = -TWO_PI * (float)md * (1.0f / (float)LL);
        sincosf(thd, &di[j], &dr[j]);
    }

#pragma unroll
    for (int o = 0; o < OUTER; o++) {
        // front-batch INNER dense float4 loads
        float4 v[INNER];
#pragma unroll
        for (int i = 0; i < INNER; i++)
            v[i] = __ldg(base4 + (size_t)(o * INNER + i) * TPB + tid);

#pragma unroll
        for (int i = 0; i < INNER; i++) {
            float x = active ? v[i].x : 0.0f;
#pragma unroll
            for (int j = 0; j < NCC; j++) {
                re[j] = fmaf(x, cr[j], re[j]);
                im[j] = fmaf(x, ci[j], im[j]);
                float cn = cr[j] * dr[j] - ci[j] * di[j];
                ci[j]    = fmaf(ci[j], dr[j], cr[j] * di[j]);
                cr[j]    = cn;
            }
        }
    }

    // ---- warp reduction (inactive lanes contribute exact zeros) ----
#pragma unroll
    for (int off = 16; off > 0; off >>= 1) {
#pragma unroll
        for (int j = 0; j < NCC; j++) {
            re[j] += __shfl_xor_sync(0xffffffffu, re[j], off);
            im[j] += __shfl_xor_sync(0xffffffffu, im[j], off);
        }
    }

    __shared__ float sred[32][8];   // [warp][re0..3, im0..3]
    __shared__ float fwsh[8];

    const int wid  = tid >> 5;
    const int lane = tid & 31;
    if (lane == 0) {
#pragma unroll
        for (int j = 0; j < NCC; j++) {
            sred[wid][j]     = re[j];
            sred[wid][4 + j] = im[j];
        }
    }
    __syncthreads();

    if (tid < 8) {
        float v2 = 0.0f;
#pragma unroll
        for (int w = 0; w < 32; w++) v2 += sred[w][tid];
        sred[0][tid] = v2;
    }
    __syncthreads();

    if (tid < NCC) {
        float R = sred[0][tid];
        float I = sred[0][4 + tid];
        float mag = sqrtf(fmaf(R, R, I * I));
        float ph  = atan2f(I, R);
        float w   = cw[tid];
        fwsh[2 * tid]     = mag * w;
        fwsh[2 * tid + 1] = ph * w;
    }
    __syncthreads();

    // ---- projection: out[b,d] = pb[d] + sum_j fwsh[j] * pw[d*8+j] ----
    if (tid < DD) {
        float acc = pb[tid];
        const float* pwrow = pw + tid * (2 * NCC);
#pragma unroll
        for (int j = 0; j < 2 * NCC; j++)
            acc = fmaf(fwsh[j], pwrow[j], acc);
        out[b * DD + tid] = acc;
    }
}

extern "C" void kernel_launch(void* const* d_in, const int* in_sizes, int n_in,
                              void* d_out, int out_size)
{
    const float* seq = (const float*)d_in[0];
    // d_in[1] = hidden_states: intentionally unused (reference never reads it)
    const float* cw  = (const float*)d_in[2];
    const float* pw  = (const float*)d_in[3];
    const float* pb  = (const float*)d_in[4];
    float* out       = (float*)d_out;

    cycle_detector_kernel<<<BB, TPB>>>(seq, cw, pw, pb, out);
}

// round 12
// speedup vs baseline: 1.2694x; 1.2694x over previous
#include <cuda_runtime.h>
#include <math.h>

// Problem constants (fixed by the dataset):
//   B=128, L=8192, NF=16, D=256, NC=4
//   FFT bins for CYCLES [1/12,1/4,1/2,1] @ SR=1/30, L=8192: k={23,68,137,273}
// Inputs (metadata order):
//   d_in[0] input_sequence (B,L,NF) f32   -- only channel 0 used
//   d_in[1] hidden_states  (B,L,D)  f32   -- UNUSED by reference; never read
//   d_in[2] cycle_weights  (NC,)    f32
//   d_in[3] proj_w         (D,2*NC) f32
//   d_in[4] proj_b         (D,)     f32
// Output: (B,D) f32
//
// FINAL (roofline-converged) kernel.
// Channel 0 sits at stride 64B; the DRAM atom is 64B, so mandatory traffic
// = B*L*64B = 67MB regardless of access pattern. Best measured: 67MB/8.9us
// = 7.5TB/s (~94% of HBM3e spec). Measured dead ends across the session:
//   - __ldcs streaming hint: traffic unchanged, slight loss
//   - split-2 grid=256 (all-SM coverage): neutral
//   - occupancy 80% (TPB=1024 x 2 CTA/SM): neutral
//   - cp.async.bulk double-buffered SMEM staging: loss (TMA idle)
//   - dense fully-coalesced LDG.128 full-tensor read: loss (same DRAM%,
//     4x compute) -> proves the strided path already sits at the
//     path-independent DRAM ceiling.

#define BB   128
#define LL   8192
#define NFF  16
#define DD   256
#define NCC  4
#define TPB  1024
#define ITER (LL / TPB)   // 8

__global__ __launch_bounds__(TPB)
void cycle_detector_kernel(const float* __restrict__ seq,
                           const float* __restrict__ cw,
                           const float* __restrict__ pw,   // (D, 8) row-major
                           const float* __restrict__ pb,
                           float* __restrict__ out)
{
    const int b   = blockIdx.x;
    const int tid = threadIdx.x;

    const int KIDX[NCC] = {23, 68, 137, 273};
    const float TWO_PI = 6.28318530717958647692f;

    // ---- batch all 8 strided loads up front (max MLP) ----
    const float* base = seq + (size_t)b * (size_t)(LL * NFF) + (size_t)tid * NFF;
    float x[ITER];
#pragma unroll
    for (int i = 0; i < ITER; i++)
        x[i] = __ldg(base + (size_t)i * (TPB * NFF));

    // ---- twiddles: start angle for t=tid, step for t+=TPB ----
    float re[NCC], im[NCC];
    float cr[NCC], ci[NCC];
    float dr[NCC], di[NCC];
#pragma unroll
    for (int j = 0; j < NCC; j++) {
        re[j] = 0.0f; im[j] = 0.0f;
        int m0 = (KIDX[j] * tid) & (LL - 1);
        float th0 = -TWO_PI * (float)m0 * (1.0f / (float)LL);
        sincosf(th0, &ci[j], &cr[j]);
        int md = (KIDX[j] * TPB) & (LL - 1);
        float thd = -TWO_PI * (float)md * (1.0f / (float)LL);
        sincosf(thd, &di[j], &dr[j]);
    }

#pragma unroll
    for (int i = 0; i < ITER; i++) {
#pragma unroll
        for (int j = 0; j < NCC; j++) {
            re[j] = fmaf(x[i], cr[j], re[j]);
            im[j] = fmaf(x[i], ci[j], im[j]);
            float cn = cr[j] * dr[j] - ci[j] * di[j];
            ci[j]    = fmaf(ci[j], dr[j], cr[j] * di[j]);
            cr[j]    = cn;
        }
    }

    // ---- warp reduction ----
#pragma unroll
    for (int off = 16; off > 0; off >>= 1) {
#pragma unroll
        for (int j = 0; j < NCC; j++) {
            re[j] += __shfl_xor_sync(0xffffffffu, re[j], off);
            im[j] += __shfl_xor_sync(0xffffffffu, im[j], off);
        }
    }

    __shared__ float sred[32][8];   // [warp][re0..3, im0..3]
    __shared__ float fwsh[8];       // weighted features (mag,phase interleaved)

    const int wid  = tid >> 5;
    const int lane = tid & 31;
    if (lane == 0) {
#pragma unroll
        for (int j = 0; j < NCC; j++) {
            sred[wid][j]     = re[j];
            sred[wid][4 + j] = im[j];
        }
    }
    __syncthreads();

    if (tid < 8) {
        float v = 0.0f;
#pragma unroll
        for (int w = 0; w < 32; w++) v += sred[w][tid];
        sred[0][tid] = v;   // final bin sums live in row 0
    }
    __syncthreads();

    if (tid < NCC) {
        float R = sred[0][tid];
        float I = sred[0][4 + tid];
        float mag = sqrtf(fmaf(R, R, I * I));
        float ph  = atan2f(I, R);
        float w   = cw[tid];
        fwsh[2 * tid]     = mag * w;
        fwsh[2 * tid + 1] = ph * w;
    }
    __syncthreads();

    // ---- projection: out[b,d] = pb[d] + sum_j fwsh[j] * pw[d*8+j] ----
    if (tid < DD) {
        float acc = pb[tid];
        const float* pwrow = pw + tid * (2 * NCC);
#pragma unroll
        for (int j = 0; j < 2 * NCC; j++)
            acc = fmaf(fwsh[j], pwrow[j], acc);
        out[b * DD + tid] = acc;
    }
}

extern "C" void kernel_launch(void* const* d_in, const int* in_sizes, int n_in,
                              void* d_out, int out_size)
{
    const float* seq = (const float*)d_in[0];
    // d_in[1] = hidden_states: intentionally unused (reference never reads it)
    const float* cw  = (const float*)d_in[2];
    const float* pw  = (const float*)d_in[3];
    const float* pb  = (const float*)d_in[4];
    float* out       = (float*)d_out;

    cycle_detector_kernel<<<BB, TPB>>>(seq, cw, pw, pb, out);
}